// round 1
// baseline (speedup 1.0000x reference)
#include <cuda_runtime.h>
#include <cstdint>

#define BB 16
#define NN 1024
#define FIN 64
#define HH 256
#define NEGV (-9e15f)
#define TM 16

// ---------------- scratch (no allocs allowed) ----------------
__device__ float g_x[BB * NN * HH];   // 16 MB
__device__ float g_h[BB * NN * HH];   // 16 MB
__device__ float g_s1[BB * NN];
__device__ float g_s2[BB * NN];

typedef unsigned long long u64;

__device__ __forceinline__ u64 pack2(float x) {
    u64 r; asm("mov.b64 %0, {%1, %1};" : "=l"(r) : "f"(x)); return r;
}
__device__ __forceinline__ void ffma2(u64& d, u64 a, u64 b) {
    asm("fma.rn.f32x2 %0, %1, %2, %0;" : "+l"(d) : "l"(a), "l"(b));
}
__device__ __forceinline__ float2 unpack2(u64 v) {
    float2 r; asm("mov.b64 {%0, %1}, %2;" : "=f"(r.x), "=f"(r.y) : "l"(v)); return r;
}

// ---------------- embed: out[M,256] = nf[M,64] @ W[64,256] + b ----------------
__global__ __launch_bounds__(256) void embed_kernel(
    const float* __restrict__ nf, const float* __restrict__ W,
    const float* __restrict__ bias, float* __restrict__ out)
{
    __shared__ float xs[FIN * TM];   // xs[k*TM + r]
    const int row0 = blockIdx.x * TM;
    const int tid = threadIdx.x;

    for (int t = tid; t < FIN * TM; t += 256) {
        int r = t >> 6, k = t & 63;
        xs[k * TM + r] = nf[(size_t)(row0 + r) * FIN + k];
    }
    __syncthreads();

    u64 acc[TM / 2];
#pragma unroll
    for (int p = 0; p < TM / 2; p++) acc[p] = 0ULL;

    const int c = tid;
#pragma unroll 4
    for (int k = 0; k < FIN; k++) {
        u64 w2 = pack2(W[k * HH + c]);
        const ulonglong2* ap = (const ulonglong2*)(xs + k * TM);
        ulonglong2 q0 = ap[0], q1 = ap[1], q2 = ap[2], q3 = ap[3];
        ffma2(acc[0], q0.x, w2); ffma2(acc[1], q0.y, w2);
        ffma2(acc[2], q1.x, w2); ffma2(acc[3], q1.y, w2);
        ffma2(acc[4], q2.x, w2); ffma2(acc[5], q2.y, w2);
        ffma2(acc[6], q3.x, w2); ffma2(acc[7], q3.y, w2);
    }
    const float bv = bias[c];
#pragma unroll
    for (int p = 0; p < TM / 2; p++) {
        float2 v = unpack2(acc[p]);
        out[(size_t)(row0 + 2 * p) * HH + c]     = v.x + bv;
        out[(size_t)(row0 + 2 * p + 1) * HH + c] = v.y + bv;
    }
}

// ---------------- gemm256: out[M,256] = X[M,256] @ W[256,256] ----------------
__global__ __launch_bounds__(256) void gemm256_kernel(
    const float* __restrict__ X, const float* __restrict__ W,
    float* __restrict__ out)
{
    __shared__ float xs[HH * TM];    // 16KB, xs[k*TM + r]
    const int row0 = blockIdx.x * TM;
    const int tid = threadIdx.x;

    for (int t = tid; t < HH * TM; t += 256) {
        int r = t >> 8, k = t & 255;
        xs[k * TM + r] = X[(size_t)(row0 + r) * HH + k];
    }
    __syncthreads();

    u64 acc[TM / 2];
#pragma unroll
    for (int p = 0; p < TM / 2; p++) acc[p] = 0ULL;

    const int c = tid;
#pragma unroll 4
    for (int k = 0; k < HH; k++) {
        u64 w2 = pack2(W[k * HH + c]);
        const ulonglong2* ap = (const ulonglong2*)(xs + k * TM);
        ulonglong2 q0 = ap[0], q1 = ap[1], q2 = ap[2], q3 = ap[3];
        ffma2(acc[0], q0.x, w2); ffma2(acc[1], q0.y, w2);
        ffma2(acc[2], q1.x, w2); ffma2(acc[3], q1.y, w2);
        ffma2(acc[4], q2.x, w2); ffma2(acc[5], q2.y, w2);
        ffma2(acc[6], q3.x, w2); ffma2(acc[7], q3.y, w2);
    }
#pragma unroll
    for (int p = 0; p < TM / 2; p++) {
        float2 v = unpack2(acc[p]);
        out[(size_t)(row0 + 2 * p) * HH + c]     = v.x;
        out[(size_t)(row0 + 2 * p + 1) * HH + c] = v.y;
    }
}

// ---------------- s1/s2: per-row dots of h with a1,a2 ----------------
__global__ __launch_bounds__(256) void s1s2_kernel(
    const float* __restrict__ h, const float* __restrict__ a1,
    const float* __restrict__ a2, float* __restrict__ s1, float* __restrict__ s2)
{
    const int row = blockIdx.x * 8 + (threadIdx.x >> 5);
    const int lane = threadIdx.x & 31;
    const float* hr = h + (size_t)row * HH;
    float v1 = 0.f, v2 = 0.f;
#pragma unroll
    for (int c = lane; c < HH; c += 32) {
        float hv = hr[c];
        v1 += hv * a1[c];
        v2 += hv * a2[c];
    }
#pragma unroll
    for (int o = 16; o; o >>= 1) {
        v1 += __shfl_xor_sync(0xffffffffu, v1, o);
        v2 += __shfl_xor_sync(0xffffffffu, v2, o);
    }
    if (lane == 0) { s1[row] = v1; s2[row] = v2; }
}

// ---------------- attention: out = relu(softmax(mask(leaky(s1_i+s2_j))) @ h) ----------------
__global__ __launch_bounds__(256) void att_kernel(
    const float* __restrict__ adj, const float* __restrict__ h,
    const float* __restrict__ s1, const float* __restrict__ s2,
    float* __restrict__ out)
{
    extern __shared__ float att[];       // [NN * 16], att[j*16 + r] (unnormalized probs)
    __shared__ float red[8];
    __shared__ float bcastM;
    __shared__ float rowsum_s[16];

    const int b = blockIdx.y;
    const int i0 = blockIdx.x * 16;
    const int tid = threadIdx.x;
    const int lane = tid & 31, wid = tid >> 5;

    const float* adjb = adj + ((size_t)b * NN + i0) * NN;
    const float* s2b = s2 + b * NN;

    for (int r = 0; r < 16; r++) {
        const float s1i = s1[b * NN + i0 + r];
        float ev[4];
        float m = NEGV;
#pragma unroll
        for (int jj = 0; jj < 4; jj++) {
            int j = jj * 256 + tid;
            float a = adjb[(size_t)r * NN + j];
            float e = s1i + s2b[j];
            e = (e >= 0.f) ? e : 0.2f * e;          // LeakyReLU(0.2)
            e = (a > 0.f) ? e : NEGV;               // mask
            ev[jj] = e;
            m = fmaxf(m, e);
        }
#pragma unroll
        for (int o = 16; o; o >>= 1) m = fmaxf(m, __shfl_xor_sync(0xffffffffu, m, o));
        if (lane == 0) red[wid] = m;
        __syncthreads();
        if (tid == 0) {
            float mm = red[0];
#pragma unroll
            for (int w = 1; w < 8; w++) mm = fmaxf(mm, red[w]);
            bcastM = mm;
        }
        __syncthreads();
        m = bcastM;

        float sum = 0.f;
#pragma unroll
        for (int jj = 0; jj < 4; jj++) {
            float p = __expf(ev[jj] - m);
            att[(jj * 256 + tid) * 16 + r] = p;
            sum += p;
        }
#pragma unroll
        for (int o = 16; o; o >>= 1) sum += __shfl_xor_sync(0xffffffffu, sum, o);
        if (lane == 0) red[wid] = sum;
        __syncthreads();
        if (tid == 0) {
            float ss = 0.f;
#pragma unroll
            for (int w = 0; w < 8; w++) ss += red[w];
            rowsum_s[r] = ss;
        }
        __syncthreads();
    }
    __syncthreads();

    // Phase B: acc[r] = sum_j p[r][j] * h[b][j][c], packed as row-pairs (f32x2)
    u64 acc[8];
#pragma unroll
    for (int p = 0; p < 8; p++) acc[p] = 0ULL;

    const float* hp = h + (size_t)b * NN * HH + tid;
#pragma unroll 8
    for (int j = 0; j < NN; j++) {
        u64 h2 = pack2(hp[(size_t)j * HH]);
        const ulonglong2* ap = (const ulonglong2*)(att + j * 16);
        ulonglong2 q0 = ap[0], q1 = ap[1], q2 = ap[2], q3 = ap[3];
        ffma2(acc[0], q0.x, h2); ffma2(acc[1], q0.y, h2);
        ffma2(acc[2], q1.x, h2); ffma2(acc[3], q1.y, h2);
        ffma2(acc[4], q2.x, h2); ffma2(acc[5], q2.y, h2);
        ffma2(acc[6], q3.x, h2); ffma2(acc[7], q3.y, h2);
    }

    float* ob = out + ((size_t)b * NN + i0) * HH + tid;
#pragma unroll
    for (int p = 0; p < 8; p++) {
        float2 v = unpack2(acc[p]);
        float o0 = v.x / rowsum_s[2 * p];
        float o1 = v.y / rowsum_s[2 * p + 1];
        ob[(size_t)(2 * p) * HH]     = fmaxf(o0, 0.f);   // ReLU
        ob[(size_t)(2 * p + 1) * HH] = fmaxf(o1, 0.f);
    }
}

// ---------------- pool (mean+max over N) + 2-layer MLP ----------------
__global__ __launch_bounds__(256) void pool_mlp_kernel(
    const float* __restrict__ x, const float* __restrict__ W1,
    const float* __restrict__ b1, const float* __restrict__ W2,
    const float* __restrict__ b2, float* __restrict__ gout)
{
    __shared__ float g0[HH];
    __shared__ float t1[HH];
    const int b = blockIdx.x, c = threadIdx.x;
    const float* xb = x + (size_t)b * NN * HH + c;

    float s = 0.f, m = -3.4e38f;
#pragma unroll 8
    for (int n = 0; n < NN; n++) {
        float v = xb[(size_t)n * HH];
        s += v;
        m = fmaxf(m, v);
    }
    g0[c] = s * (1.0f / NN) + m;
    __syncthreads();

    float a = b1[c];
#pragma unroll 4
    for (int k = 0; k < HH; k++) a += g0[k] * W1[k * HH + c];
    t1[c] = fmaxf(a, 0.f);
    __syncthreads();

    float a2 = b2[c];
#pragma unroll 4
    for (int k = 0; k < HH; k++) a2 += t1[k] * W2[k * HH + c];
    gout[b * HH + c] = a2;
}

// ---------------- launch ----------------
extern "C" void kernel_launch(void* const* d_in, const int* in_sizes, int n_in,
                              void* d_out, int out_size)
{
    const float* nf   = (const float*)d_in[0];
    const float* adj  = (const float*)d_in[1];
    const float* embW = (const float*)d_in[2];
    const float* embB = (const float*)d_in[3];
    const float* W0   = (const float*)d_in[4];
    const float* a10  = (const float*)d_in[5];
    const float* a20  = (const float*)d_in[6];
    const float* W1   = (const float*)d_in[7];
    const float* a11  = (const float*)d_in[8];
    const float* a21  = (const float*)d_in[9];
    const float* gW1  = (const float*)d_in[10];
    const float* gb1  = (const float*)d_in[11];
    const float* gW2  = (const float*)d_in[12];
    const float* gb2  = (const float*)d_in[13];

    float* out  = (float*)d_out;
    float* xout = out;                              // [B,N,H]
    float* gout = out + (size_t)BB * NN * HH;       // [B,H]

    float *xb, *hb, *s1b, *s2b;
    cudaGetSymbolAddress((void**)&xb,  g_x);
    cudaGetSymbolAddress((void**)&hb,  g_h);
    cudaGetSymbolAddress((void**)&s1b, g_s1);
    cudaGetSymbolAddress((void**)&s2b, g_s2);

    cudaFuncSetAttribute(att_kernel, cudaFuncAttributeMaxDynamicSharedMemorySize, 64 * 1024);

    dim3 blk(256);
    const int mrows = BB * NN;

    embed_kernel<<<mrows / TM, blk>>>(nf, embW, embB, xb);

    // layer 0
    gemm256_kernel<<<mrows / TM, blk>>>(xb, W0, hb);
    s1s2_kernel<<<mrows / 8, blk>>>(hb, a10, a20, s1b, s2b);
    att_kernel<<<dim3(NN / 16, BB), blk, 64 * 1024>>>(adj, hb, s1b, s2b, xb);

    // layer 1
    gemm256_kernel<<<mrows / TM, blk>>>(xb, W1, hb);
    s1s2_kernel<<<mrows / 8, blk>>>(hb, a11, a21, s1b, s2b);
    att_kernel<<<dim3(NN / 16, BB), blk, 64 * 1024>>>(adj, hb, s1b, s2b, xout);

    // pooling + MLP head
    pool_mlp_kernel<<<BB, blk>>>(xout, gW1, gb1, gW2, gb2, gout);
}

// round 3
// speedup vs baseline: 1.3401x; 1.3401x over previous
#include <cuda_runtime.h>
#include <cstdint>

#define BB 16
#define NN 1024
#define FIN 64
#define HH 256

// ---------------- scratch (no allocs allowed) ----------------
__device__ float g_x[BB * NN * HH];   // 16 MB
__device__ float g_h[BB * NN * HH];   // 16 MB
__device__ float g_s1[BB * NN];
__device__ float g_s2[BB * NN];

typedef unsigned long long u64;

__device__ __forceinline__ u64 pack2(float x) {
    u64 r; asm("mov.b64 %0, {%1, %1};" : "=l"(r) : "f"(x)); return r;
}
__device__ __forceinline__ void ffma2(u64& d, u64 a, u64 b) {
    asm("fma.rn.f32x2 %0, %1, %2, %0;" : "+l"(d) : "l"(a), "l"(b));
}
__device__ __forceinline__ float2 unpack2(u64 v) {
    float2 r; asm("mov.b64 {%0, %1}, %2;" : "=f"(r.x), "=f"(r.y) : "l"(v)); return r;
}
__device__ __forceinline__ float leaky(float x) { return x >= 0.f ? x : 0.2f * x; }

// ============================================================================
// embed: out[M,256] = nf[M,64] @ W[64,256] + b    (16 rows/block, 128 threads,
// each thread owns columns c and c+128)
// ============================================================================
__global__ __launch_bounds__(128) void embed_kernel(
    const float* __restrict__ nf, const float* __restrict__ W,
    const float* __restrict__ bias, float* __restrict__ out)
{
    __shared__ float xs[4 * FIN * 4];     // [g][k][q], g=row>>2, q=row&3
    const int row0 = blockIdx.x * 16;
    const int tid = threadIdx.x;

    // loader: 4 g * 64 k = 256 float4 tasks / 128 threads = 2 iters
#pragma unroll
    for (int it = 0; it < 2; it++) {
        int idx = it * 128 + tid;
        int g = idx >> 6, k = idx & 63;
        float4 v;
        v.x = nf[(size_t)(row0 + 4 * g + 0) * FIN + k];
        v.y = nf[(size_t)(row0 + 4 * g + 1) * FIN + k];
        v.z = nf[(size_t)(row0 + 4 * g + 2) * FIN + k];
        v.w = nf[(size_t)(row0 + 4 * g + 3) * FIN + k];
        *(float4*)(xs + g * (FIN * 4) + k * 4) = v;
    }
    __syncthreads();

    u64 accA[8], accB[8];
#pragma unroll
    for (int p = 0; p < 8; p++) { accA[p] = 0ULL; accB[p] = 0ULL; }

    const int c = tid;
    float wA[4], wB[4];
#pragma unroll
    for (int u = 0; u < 4; u++) { wA[u] = W[u * HH + c]; wB[u] = W[u * HH + c + 128]; }

    for (int kt = 0; kt < FIN; kt += 4) {
        float cAv[4], cBv[4];
#pragma unroll
        for (int u = 0; u < 4; u++) { cAv[u] = wA[u]; cBv[u] = wB[u]; }
        if (kt + 4 < FIN) {
#pragma unroll
            for (int u = 0; u < 4; u++) {
                wA[u] = W[(kt + 4 + u) * HH + c];
                wB[u] = W[(kt + 4 + u) * HH + c + 128];
            }
        }
#pragma unroll
        for (int u = 0; u < 4; u++) {
            int k = kt + u;
            u64 h2a = pack2(cAv[u]);
            u64 h2b = pack2(cBv[u]);
#pragma unroll
            for (int g = 0; g < 4; g++) {
                ulonglong2 q = *(const ulonglong2*)(xs + g * (FIN * 4) + k * 4);
                ffma2(accA[2 * g], q.x, h2a); ffma2(accA[2 * g + 1], q.y, h2a);
                ffma2(accB[2 * g], q.x, h2b); ffma2(accB[2 * g + 1], q.y, h2b);
            }
        }
    }
    const float bA = bias[c], bBv = bias[c + 128];
    float* ob = out + (size_t)row0 * HH + c;
#pragma unroll
    for (int p = 0; p < 8; p++) {
        float2 vA = unpack2(accA[p]);
        float2 vB = unpack2(accB[p]);
        ob[(size_t)(2 * p) * HH]           = vA.x + bA;
        ob[(size_t)(2 * p + 1) * HH]       = vA.y + bA;
        ob[(size_t)(2 * p) * HH + 128]     = vB.x + bBv;
        ob[(size_t)(2 * p + 1) * HH + 128] = vB.y + bBv;
    }
}

// ============================================================================
// gemm256 + fused s1/s2:  h = X @ W ;  s1[m] = h[m]·a1 ; s2[m] = h[m]·a2
// ============================================================================
__global__ __launch_bounds__(128) void gemm_s1s2_kernel(
    const float* __restrict__ X, const float* __restrict__ W,
    const float* __restrict__ a1, const float* __restrict__ a2,
    float* __restrict__ hout, float* __restrict__ s1o, float* __restrict__ s2o)
{
    __shared__ float xs[4 * HH * 4];       // 16KB  [g][k][q]
    __shared__ float red[128];             // [r][warp] for s1 (0..63) and s2 (64..127)
    const int row0 = blockIdx.x * 16;
    const int tid = threadIdx.x;
    const int lane = tid & 31, wid = tid >> 5;

    // loader: 4 g * 256 k = 1024 float4 tasks / 128 threads = 8 iters
#pragma unroll
    for (int it = 0; it < 8; it++) {
        int idx = it * 128 + tid;
        int g = idx >> 8, k = idx & 255;
        float4 v;
        v.x = X[(size_t)(row0 + 4 * g + 0) * HH + k];
        v.y = X[(size_t)(row0 + 4 * g + 1) * HH + k];
        v.z = X[(size_t)(row0 + 4 * g + 2) * HH + k];
        v.w = X[(size_t)(row0 + 4 * g + 3) * HH + k];
        *(float4*)(xs + g * (HH * 4) + k * 4) = v;
    }
    __syncthreads();

    u64 accA[8], accB[8];
#pragma unroll
    for (int p = 0; p < 8; p++) { accA[p] = 0ULL; accB[p] = 0ULL; }

    const int c = tid;
    float wA[4], wB[4];
#pragma unroll
    for (int u = 0; u < 4; u++) { wA[u] = W[u * HH + c]; wB[u] = W[u * HH + c + 128]; }

    for (int kt = 0; kt < HH; kt += 4) {
        float cAv[4], cBv[4];
#pragma unroll
        for (int u = 0; u < 4; u++) { cAv[u] = wA[u]; cBv[u] = wB[u]; }
        if (kt + 4 < HH) {
#pragma unroll
            for (int u = 0; u < 4; u++) {
                wA[u] = W[(kt + 4 + u) * HH + c];
                wB[u] = W[(kt + 4 + u) * HH + c + 128];
            }
        }
#pragma unroll
        for (int u = 0; u < 4; u++) {
            int k = kt + u;
            u64 h2a = pack2(cAv[u]);
            u64 h2b = pack2(cBv[u]);
#pragma unroll
            for (int g = 0; g < 4; g++) {
                ulonglong2 q = *(const ulonglong2*)(xs + g * (HH * 4) + k * 4);
                ffma2(accA[2 * g], q.x, h2a); ffma2(accA[2 * g + 1], q.y, h2a);
                ffma2(accB[2 * g], q.x, h2b); ffma2(accB[2 * g + 1], q.y, h2b);
            }
        }
    }

    // epilogue: store h, accumulate s1/s2 partials
    const float a1A = a1[c], a1B = a1[c + 128];
    const float a2A = a2[c], a2B = a2[c + 128];
    float s1p[16], s2p[16];
    float* ob = hout + (size_t)row0 * HH + c;
#pragma unroll
    for (int p = 0; p < 8; p++) {
        float2 vA = unpack2(accA[p]);
        float2 vB = unpack2(accB[p]);
        ob[(size_t)(2 * p) * HH]           = vA.x;
        ob[(size_t)(2 * p + 1) * HH]       = vA.y;
        ob[(size_t)(2 * p) * HH + 128]     = vB.x;
        ob[(size_t)(2 * p + 1) * HH + 128] = vB.y;
        s1p[2 * p]     = vA.x * a1A + vB.x * a1B;
        s1p[2 * p + 1] = vA.y * a1A + vB.y * a1B;
        s2p[2 * p]     = vA.x * a2A + vB.x * a2B;
        s2p[2 * p + 1] = vA.y * a2A + vB.y * a2B;
    }
#pragma unroll
    for (int r = 0; r < 16; r++) {
#pragma unroll
        for (int o = 16; o; o >>= 1) {
            s1p[r] += __shfl_xor_sync(0xffffffffu, s1p[r], o);
            s2p[r] += __shfl_xor_sync(0xffffffffu, s2p[r], o);
        }
        if (lane == 0) { red[r * 4 + wid] = s1p[r]; red[64 + r * 4 + wid] = s2p[r]; }
    }
    __syncthreads();
    if (tid < 32) {
        int r = tid & 15;
        int base = (tid < 16) ? 0 : 64;
        float s = red[base + r * 4] + red[base + r * 4 + 1] + red[base + r * 4 + 2] + red[base + r * 4 + 3];
        if (tid < 16) s1o[row0 + r] = s; else s2o[row0 + r] = s;
    }
}

// ============================================================================
// attention: out = relu( softmax_row( mask( leaky(s1_i + s2_j) ) ) @ h )
// block: 128 threads, 16 rows, batch b.  att smem layout [g][j][q] (row quads).
// Uses shift m_i = leaky(s1_i + max_j s2_j)  (softmax is shift-invariant).
// ============================================================================
__global__ __launch_bounds__(128) void att_kernel(
    const float* __restrict__ adj, const float* __restrict__ h,
    const float* __restrict__ s1, const float* __restrict__ s2,
    float* __restrict__ out)
{
    extern __shared__ float att[];        // 4 groups * 1024 j * 4 = 16384 floats (64KB)
    __shared__ float red[64];
    __shared__ float rinv[16];
    __shared__ float s2max_sh;

    const int b = blockIdx.y;
    const int i0 = blockIdx.x * 16;
    const int tid = threadIdx.x;
    const int lane = tid & 31, wid = tid >> 5;

    const float* s2b = s2 + b * NN;
    float s2v[8];
    float m = -3.4e38f;
#pragma unroll
    for (int u = 0; u < 8; u++) { s2v[u] = s2b[u * 128 + tid]; m = fmaxf(m, s2v[u]); }
#pragma unroll
    for (int o = 16; o; o >>= 1) m = fmaxf(m, __shfl_xor_sync(0xffffffffu, m, o));
    if (lane == 0) red[wid] = m;
    __syncthreads();
    if (tid == 0) s2max_sh = fmaxf(fmaxf(red[0], red[1]), fmaxf(red[2], red[3]));
    __syncthreads();
    const float s2max = s2max_sh;

    const float* adjb = adj + ((size_t)b * NN + i0) * NN;

    // -------- phase A: unnormalized probs into att, rowsum partials --------
#pragma unroll
    for (int g = 0; g < 4; g++) {
        float s1v[4], mi[4], sum[4];
#pragma unroll
        for (int q = 0; q < 4; q++) {
            s1v[q] = s1[b * NN + i0 + 4 * g + q];
            mi[q] = leaky(s1v[q] + s2max);
            sum[q] = 0.f;
        }
#pragma unroll 2
        for (int u = 0; u < 8; u++) {
            int j = u * 128 + tid;
            float s2j = s2v[u];
            float4 pv;
            float aq[4];
#pragma unroll
            for (int q = 0; q < 4; q++) aq[q] = adjb[(size_t)(4 * g + q) * NN + j];
            {
                float e = leaky(s1v[0] + s2j);
                pv.x = (aq[0] > 0.f) ? __expf(e - mi[0]) : 0.f; sum[0] += pv.x;
                e = leaky(s1v[1] + s2j);
                pv.y = (aq[1] > 0.f) ? __expf(e - mi[1]) : 0.f; sum[1] += pv.y;
                e = leaky(s1v[2] + s2j);
                pv.z = (aq[2] > 0.f) ? __expf(e - mi[2]) : 0.f; sum[2] += pv.z;
                e = leaky(s1v[3] + s2j);
                pv.w = (aq[3] > 0.f) ? __expf(e - mi[3]) : 0.f; sum[3] += pv.w;
            }
            *(float4*)(att + g * 4096 + j * 4) = pv;   // conflict-free STS.128
        }
#pragma unroll
        for (int q = 0; q < 4; q++) {
#pragma unroll
            for (int o = 16; o; o >>= 1) sum[q] += __shfl_xor_sync(0xffffffffu, sum[q], o);
            if (lane == 0) red[(4 * g + q) * 4 + wid] = sum[q];
        }
    }
    __syncthreads();
    if (tid < 16) {
        float s = red[tid * 4] + red[tid * 4 + 1] + red[tid * 4 + 2] + red[tid * 4 + 3];
        rinv[tid] = 1.0f / s;
    }
    __syncthreads();

    // -------- phase B: C[16,256] = att[16,1024] @ h[1024,256], f32x2 FMAs ----
    u64 accA[8], accB[8];
#pragma unroll
    for (int p = 0; p < 8; p++) { accA[p] = 0ULL; accB[p] = 0ULL; }

    const float* hpA = h + (size_t)b * NN * HH + tid;      // col c = tid
    const float* hpB = hpA + 128;                          // col c+128
    float hA[4], hB[4];
#pragma unroll
    for (int u = 0; u < 4; u++) { hA[u] = hpA[(size_t)u * HH]; hB[u] = hpB[(size_t)u * HH]; }

    for (int jt = 0; jt < NN; jt += 4) {
        float cAv[4], cBv[4];
#pragma unroll
        for (int u = 0; u < 4; u++) { cAv[u] = hA[u]; cBv[u] = hB[u]; }
        if (jt + 4 < NN) {
#pragma unroll
            for (int u = 0; u < 4; u++) {
                hA[u] = hpA[(size_t)(jt + 4 + u) * HH];
                hB[u] = hpB[(size_t)(jt + 4 + u) * HH];
            }
        }
#pragma unroll
        for (int u = 0; u < 4; u++) {
            int j = jt + u;
            u64 h2a = pack2(cAv[u]);
            u64 h2b = pack2(cBv[u]);
#pragma unroll
            for (int g = 0; g < 4; g++) {
                ulonglong2 q = *(const ulonglong2*)(att + g * 4096 + j * 4);
                ffma2(accA[2 * g], q.x, h2a); ffma2(accA[2 * g + 1], q.y, h2a);
                ffma2(accB[2 * g], q.x, h2b); ffma2(accB[2 * g + 1], q.y, h2b);
            }
        }
    }

    float* ob = out + ((size_t)b * NN + i0) * HH + tid;
#pragma unroll
    for (int p = 0; p < 8; p++) {
        float2 vA = unpack2(accA[p]);
        float2 vB = unpack2(accB[p]);
        float i0v = rinv[2 * p], i1v = rinv[2 * p + 1];
        ob[(size_t)(2 * p) * HH]           = fmaxf(vA.x * i0v, 0.f);
        ob[(size_t)(2 * p + 1) * HH]       = fmaxf(vA.y * i1v, 0.f);
        ob[(size_t)(2 * p) * HH + 128]     = fmaxf(vB.x * i0v, 0.f);
        ob[(size_t)(2 * p + 1) * HH + 128] = fmaxf(vB.y * i1v, 0.f);
    }
}

// ---------------- pool (mean+max over N) + 2-layer MLP ----------------
__global__ __launch_bounds__(256) void pool_mlp_kernel(
    const float* __restrict__ x, const float* __restrict__ W1,
    const float* __restrict__ b1, const float* __restrict__ W2,
    const float* __restrict__ b2, float* __restrict__ gout)
{
    __shared__ float g0[HH];
    __shared__ float t1[HH];
    const int b = blockIdx.x, c = threadIdx.x;
    const float* xb = x + (size_t)b * NN * HH + c;

    float s = 0.f, m = -3.4e38f;
#pragma unroll 8
    for (int n = 0; n < NN; n++) {
        float v = xb[(size_t)n * HH];
        s += v;
        m = fmaxf(m, v);
    }
    g0[c] = s * (1.0f / NN) + m;
    __syncthreads();

    float a = b1[c];
#pragma unroll 4
    for (int k = 0; k < HH; k++) a += g0[k] * W1[k * HH + c];
    t1[c] = fmaxf(a, 0.f);
    __syncthreads();

    float a2 = b2[c];
#pragma unroll 4
    for (int k = 0; k < HH; k++) a2 += t1[k] * W2[k * HH + c];
    gout[b * HH + c] = a2;
}

// ---------------- launch ----------------
extern "C" void kernel_launch(void* const* d_in, const int* in_sizes, int n_in,
                              void* d_out, int out_size)
{
    const float* nf   = (const float*)d_in[0];
    const float* adj  = (const float*)d_in[1];
    const float* embW = (const float*)d_in[2];
    const float* embB = (const float*)d_in[3];
    const float* W0   = (const float*)d_in[4];
    const float* a10  = (const float*)d_in[5];
    const float* a20  = (const float*)d_in[6];
    const float* W1   = (const float*)d_in[7];
    const float* a11  = (const float*)d_in[8];
    const float* a21  = (const float*)d_in[9];
    const float* gW1  = (const float*)d_in[10];
    const float* gb1  = (const float*)d_in[11];
    const float* gW2  = (const float*)d_in[12];
    const float* gb2  = (const float*)d_in[13];

    float* out  = (float*)d_out;
    float* xout = out;                              // [B,N,H]
    float* gout = out + (size_t)BB * NN * HH;       // [B,H]

    float *xb, *hb, *s1b, *s2b;
    cudaGetSymbolAddress((void**)&xb,  g_x);
    cudaGetSymbolAddress((void**)&hb,  g_h);
    cudaGetSymbolAddress((void**)&s1b, g_s1);
    cudaGetSymbolAddress((void**)&s2b, g_s2);

    cudaFuncSetAttribute(att_kernel, cudaFuncAttributeMaxDynamicSharedMemorySize, 64 * 1024);

    const int mrows = BB * NN;
    dim3 blk128(128);

    embed_kernel<<<mrows / 16, blk128>>>(nf, embW, embB, xb);

    // layer 0
    gemm_s1s2_kernel<<<mrows / 16, blk128>>>(xb, W0, a10, a20, hb, s1b, s2b);
    att_kernel<<<dim3(NN / 16, BB), blk128, 64 * 1024>>>(adj, hb, s1b, s2b, xb);

    // layer 1
    gemm_s1s2_kernel<<<mrows / 16, blk128>>>(xb, W1, a11, a21, hb, s1b, s2b);
    att_kernel<<<dim3(NN / 16, BB), blk128, 64 * 1024>>>(adj, hb, s1b, s2b, xout);

    // pooling + MLP head
    pool_mlp_kernel<<<BB, 256>>>(xout, gW1, gb1, gW2, gb2, gout);
}